// round 6
// baseline (speedup 1.0000x reference)
#include <cuda_runtime.h>

#define N_NODES 100000
#define N_EDGES 3200000
#define D_IN    128
#define D_HID   16
#define N_CLS   2

// ---- scratch (static device memory; no runtime allocation) ----
__device__ __align__(128) float g_deg [N_NODES];
__device__ __align__(128) float g_dinv[N_NODES];
__device__ __align__(128) float g_g1  [N_NODES * D_HID];   // read-only messages L1
__device__ __align__(128) float g_acc1[N_NODES * D_HID];   // accumulator L1
__device__ __align__(128) float g_g2  [N_NODES * N_CLS];   // read-only messages L2
__device__ __align__(128) float g_acc2[N_NODES * N_CLS];   // accumulator L2

// ---- 1) degree init (self-loop contributes 1) ----
__global__ void k_init_deg() {
    int i = blockIdx.x * blockDim.x + threadIdx.x;
    if (i < N_NODES) g_deg[i] = 1.0f;
}

// ---- 2) degree count (edge_index is int32: harness dtypes are f32/i32/bf16) ----
__global__ void k_deg(const int* __restrict__ ei_dst) {
    int e = blockIdx.x * blockDim.x + threadIdx.x;
    if (e >= N_EDGES) return;
    atomicAdd(&g_deg[ei_dst[e]], 1.0f);
}

// ---- 3) h1 = x @ W1 ; g1 = h1 * dinv ; acc1 = g1 (self-loop init) ----
// 256 threads = 16 nodes x 16 output cols. N_NODES/16 = 6250 blocks exactly.
__global__ __launch_bounds__(256) void k_gemm1(const float* __restrict__ x,
                                               const float* __restrict__ W1) {
    __shared__ float Ws[D_IN * D_HID];       // 8 KB
    __shared__ float Xs[16][D_IN + 1];       // 8.25 KB (+1 pad kills bank conflicts)
    int tid = threadIdx.x;
    int nodeBase = blockIdx.x * 16;

    for (int i = tid; i < D_IN * D_HID; i += 256) Ws[i] = W1[i];
    for (int i = tid; i < 16 * D_IN; i += 256) {
        int r = i >> 7, c = i & 127;
        Xs[r][c] = x[(nodeBase + r) * D_IN + c];
    }
    __syncthreads();

    int node = tid >> 4, col = tid & 15;
    float acc = 0.f;
#pragma unroll
    for (int k = 0; k < D_IN; k++) acc += Xs[node][k] * Ws[k * D_HID + col];

    int gn = nodeBase + node;
    float dv = rsqrtf(g_deg[gn]);            // deg >= 1 always (self-loop)
    if (col == 0) g_dinv[gn] = dv;
    float g = acc * dv;
    g_g1[gn * D_HID + col]   = g;
    g_acc1[gn * D_HID + col] = g;
}

// ---- 4) layer-1 edge scatter: acc1[dst] += g1[src] (vector red, no return) ----
__global__ void k_scatter1(const int* __restrict__ ei_src,
                           const int* __restrict__ ei_dst) {
    int e = blockIdx.x * blockDim.x + threadIdx.x;
    if (e >= N_EDGES) return;
    int s = ei_src[e], d = ei_dst[e];
    const float4* gp = reinterpret_cast<const float4*>(&g_g1[s * D_HID]);
    float4 a0 = gp[0], a1 = gp[1], a2 = gp[2], a3 = gp[3];
    float* base = &g_acc1[d * D_HID];
    asm volatile("red.global.add.v4.f32 [%0], {%1,%2,%3,%4};"
                 :: "l"(base)      , "f"(a0.x), "f"(a0.y), "f"(a0.z), "f"(a0.w) : "memory");
    asm volatile("red.global.add.v4.f32 [%0], {%1,%2,%3,%4};"
                 :: "l"(base + 4)  , "f"(a1.x), "f"(a1.y), "f"(a1.z), "f"(a1.w) : "memory");
    asm volatile("red.global.add.v4.f32 [%0], {%1,%2,%3,%4};"
                 :: "l"(base + 8)  , "f"(a2.x), "f"(a2.y), "f"(a2.z), "f"(a2.w) : "memory");
    asm volatile("red.global.add.v4.f32 [%0], {%1,%2,%3,%4};"
                 :: "l"(base + 12) , "f"(a3.x), "f"(a3.y), "f"(a3.z), "f"(a3.w) : "memory");
}

// ---- 5) finish layer 1 (dinv*acc + b1, relu), then h2 = t @ W2, g2 = h2*dinv ----
__global__ void k_layer2(const float* __restrict__ b1, const float* __restrict__ W2) {
    int n = blockIdx.x * blockDim.x + threadIdx.x;
    if (n >= N_NODES) return;
    float dv = g_dinv[n];
    const float4* ap = reinterpret_cast<const float4*>(&g_acc1[n * D_HID]);
    float4 a[4] = {ap[0], ap[1], ap[2], ap[3]};
    const float* af = reinterpret_cast<const float*>(a);
    float z0 = 0.f, z1 = 0.f;
#pragma unroll
    for (int j = 0; j < D_HID; j++) {
        float t = fmaxf(fmaf(dv, af[j], __ldg(&b1[j])), 0.f);
        z0 = fmaf(t, __ldg(&W2[j * 2 + 0]), z0);
        z1 = fmaf(t, __ldg(&W2[j * 2 + 1]), z1);
    }
    float2 g = make_float2(z0 * dv, z1 * dv);
    *reinterpret_cast<float2*>(&g_g2[n * 2])   = g;
    *reinterpret_cast<float2*>(&g_acc2[n * 2]) = g;
}

// ---- 6) layer-2 edge scatter ----
__global__ void k_scatter2(const int* __restrict__ ei_src,
                           const int* __restrict__ ei_dst) {
    int e = blockIdx.x * blockDim.x + threadIdx.x;
    if (e >= N_EDGES) return;
    int s = ei_src[e], d = ei_dst[e];
    float2 g = *reinterpret_cast<const float2*>(&g_g2[s * 2]);
    asm volatile("red.global.add.v2.f32 [%0], {%1,%2};"
                 :: "l"(&g_acc2[d * 2]), "f"(g.x), "f"(g.y) : "memory");
}

// ---- 7) out = log_softmax(dinv*acc2 + b2) ----
__global__ void k_out(const float* __restrict__ b2, float* __restrict__ out) {
    int n = blockIdx.x * blockDim.x + threadIdx.x;
    if (n >= N_NODES) return;
    float dv = g_dinv[n];
    float2 a = *reinterpret_cast<const float2*>(&g_acc2[n * 2]);
    float z0 = fmaf(dv, a.x, __ldg(&b2[0]));
    float z1 = fmaf(dv, a.y, __ldg(&b2[1]));
    float m = fmaxf(z0, z1);
    float lse = m + logf(expf(z0 - m) + expf(z1 - m));
    float2 r = make_float2(z0 - lse, z1 - lse);
    *reinterpret_cast<float2*>(&out[n * 2]) = r;
}

extern "C" void kernel_launch(void* const* d_in, const int* in_sizes, int n_in,
                              void* d_out, int out_size) {
    const float* x      = (const float*)d_in[0];
    const int*   ei     = (const int*)d_in[1];          // int32 [2, E] row-major
    const int*   ei_src = ei;
    const int*   ei_dst = ei + N_EDGES;
    const float* W1     = (const float*)d_in[2];
    const float* b1     = (const float*)d_in[3];
    const float* W2     = (const float*)d_in[4];
    const float* b2     = (const float*)d_in[5];
    float* out = (float*)d_out;

    const int TB = 256;
    k_init_deg<<<(N_NODES + TB - 1) / TB, TB>>>();
    k_deg     <<<(N_EDGES + TB - 1) / TB, TB>>>(ei_dst);
    k_gemm1   <<<N_NODES / 16, 256>>>(x, W1);
    k_scatter1<<<(N_EDGES + TB - 1) / TB, TB>>>(ei_src, ei_dst);
    k_layer2  <<<(N_NODES + TB - 1) / TB, TB>>>(b1, W2);
    k_scatter2<<<(N_EDGES + TB - 1) / TB, TB>>>(ei_src, ei_dst);
    k_out     <<<(N_NODES + TB - 1) / TB, TB>>>(b2, out);
}

// round 7
// speedup vs baseline: 1.0317x; 1.0317x over previous
#include <cuda_runtime.h>

#define N_NODES 100000
#define N_EDGES 3200000
#define D_IN    128
#define D_HID   16
#define N_CLS   2

#define NB_SCAN 400          // 400 * 256 = 102400 >= N_NODES

// ---- scratch (static device memory; no runtime allocation) ----
__device__ __align__(128) int   g_cnt [NB_SCAN * 256];   // in-degree (excl self)
__device__ __align__(128) int   g_ptr [N_NODES];         // CSR row start (exclusive scan)
__device__ __align__(128) int   g_fill[N_NODES];         // fill cursor
__device__ __align__(128) int   g_bsum[512];             // block sums for scan
__device__ __align__(128) float g_dinv[N_NODES];
__device__ __align__(128) int   g_csr_src[N_EDGES];      // src ids grouped by dst
__device__ __align__(128) float g_g1  [N_NODES * D_HID]; // layer-1 messages (h1*dinv)
__device__ __align__(128) float g_g2  [N_NODES * N_CLS]; // layer-2 messages (h2*dinv)

// ---- 1) zero histogram ----
__global__ void k_zero() {
    int i = blockIdx.x * blockDim.x + threadIdx.x;
    if (i < NB_SCAN * 256) g_cnt[i] = 0;
}

// ---- 2) in-degree histogram (int atomics) ----
__global__ void k_cnt(const int* __restrict__ ei_dst) {
    int e = blockIdx.x * blockDim.x + threadIdx.x;
    if (e < N_EDGES) atomicAdd(&g_cnt[ei_dst[e]], 1);
}

// ---- 3a) per-block sums ----
__global__ __launch_bounds__(256) void k_scan1() {
    __shared__ int s[256];
    int t = threadIdx.x;
    s[t] = g_cnt[blockIdx.x * 256 + t];
    __syncthreads();
    for (int off = 128; off > 0; off >>= 1) {
        if (t < off) s[t] += s[t + off];
        __syncthreads();
    }
    if (t == 0) g_bsum[blockIdx.x] = s[0];
}

// ---- 3b) scan block sums (single block, Hillis-Steele over 512) ----
__global__ __launch_bounds__(512) void k_scan2() {
    __shared__ int s[512];
    int t = threadIdx.x;
    int v = (t < NB_SCAN) ? g_bsum[t] : 0;
    s[t] = v;
    __syncthreads();
    for (int off = 1; off < 512; off <<= 1) {
        int a = (t >= off) ? s[t - off] : 0;
        __syncthreads();
        s[t] += a;
        __syncthreads();
    }
    if (t < NB_SCAN) g_bsum[t] = s[t] - v;   // exclusive block offset
}

// ---- 3c) per-block exclusive scan + offsets; also dinv, fill init ----
__global__ __launch_bounds__(256) void k_scan3() {
    __shared__ int s[256];
    int t = threadIdx.x;
    int i = blockIdx.x * 256 + t;
    int v = g_cnt[i];
    s[t] = v;
    __syncthreads();
    for (int off = 1; off < 256; off <<= 1) {
        int a = (t >= off) ? s[t - off] : 0;
        __syncthreads();
        s[t] += a;
        __syncthreads();
    }
    int excl = s[t] - v + g_bsum[blockIdx.x];
    if (i < N_NODES) {
        g_ptr[i]  = excl;
        g_fill[i] = excl;
        g_dinv[i] = rsqrtf((float)(v + 1));   // +1 self-loop
    }
}

// ---- 4) fill CSR: src ids grouped by dst ----
__global__ void k_fill(const int* __restrict__ ei_src,
                       const int* __restrict__ ei_dst) {
    int e = blockIdx.x * blockDim.x + threadIdx.x;
    if (e >= N_EDGES) return;
    int pos = atomicAdd(&g_fill[ei_dst[e]], 1);
    g_csr_src[pos] = ei_src[e];
}

// ---- 5) g1 = (x @ W1) * dinv ----
// 256 threads = 16 nodes x 16 cols. N_NODES/16 = 6250 blocks exactly.
__global__ __launch_bounds__(256) void k_gemm1(const float* __restrict__ x,
                                               const float* __restrict__ W1) {
    __shared__ float Ws[D_IN * D_HID];
    __shared__ float Xs[16][D_IN + 1];
    int tid = threadIdx.x;
    int nodeBase = blockIdx.x * 16;

    for (int i = tid; i < D_IN * D_HID; i += 256) Ws[i] = W1[i];
    for (int i = tid; i < 16 * D_IN; i += 256) {
        int r = i >> 7, c = i & 127;
        Xs[r][c] = x[(nodeBase + r) * D_IN + c];
    }
    __syncthreads();

    int node = tid >> 4, col = tid & 15;
    float acc = 0.f;
#pragma unroll
    for (int k = 0; k < D_IN; k++) acc += Xs[node][k] * Ws[k * D_HID + col];

    int gn = nodeBase + node;
    g_g1[gn * D_HID + col] = acc * g_dinv[gn];
}

// ---- 6) layer-1 gather + fused layer-2 node GEMM ----
// warp per node; half-warp per edge (16 lanes read one 64B g1 row).
// acc_j = g1[n][j] + sum_{s in N(n)} g1[s][j]
// t_j = relu(dinv*acc_j + b1_j);  z_c = sum_j t_j * W2[j][c];  g2 = z * dinv
__global__ __launch_bounds__(256) void k_gather1(const float* __restrict__ b1,
                                                 const float* __restrict__ W2) {
    int warp = (blockIdx.x * blockDim.x + threadIdx.x) >> 5;   // == node id
    int lane = threadIdx.x & 31;
    int half = lane >> 4;
    int j    = lane & 15;
    int n = warp;   // grid sized exactly: 12500*8 warps = 100000

    int ptr = g_ptr[n];
    int deg = g_cnt[n];

    float acc = (half == 0) ? g_g1[n * D_HID + j] : 0.f;   // self-loop
    for (int i = half; i < deg; i += 2) {
        int s = g_csr_src[ptr + i];
        acc += g_g1[s * D_HID + j];
    }
    acc += __shfl_down_sync(0xffffffffu, acc, 16);          // lanes 0..15 hold sums

    float dv = g_dinv[n];
    float t  = fmaxf(fmaf(dv, acc, __ldg(&b1[j])), 0.f);
    float p0 = t * __ldg(&W2[j * 2 + 0]);
    float p1 = t * __ldg(&W2[j * 2 + 1]);
#pragma unroll
    for (int off = 8; off >= 1; off >>= 1) {
        p0 += __shfl_down_sync(0xffffffffu, p0, off);
        p1 += __shfl_down_sync(0xffffffffu, p1, off);
    }
    if (lane == 0)
        *reinterpret_cast<float2*>(&g_g2[n * 2]) = make_float2(p0 * dv, p1 * dv);
}

// ---- 7) layer-2 gather + fused log_softmax ----
// warp per node; 2 lanes per edge (16 edges per warp iteration).
__global__ __launch_bounds__(256) void k_gather2(const float* __restrict__ b2,
                                                 float* __restrict__ out) {
    int warp = (blockIdx.x * blockDim.x + threadIdx.x) >> 5;
    int lane = threadIdx.x & 31;
    int c = lane & 1;
    int n = warp;

    int ptr = g_ptr[n];
    int deg = g_cnt[n];

    float acc = (lane < 2) ? g_g2[n * 2 + c] : 0.f;        // self-loop
    for (int i = lane >> 1; i < deg; i += 16) {
        int s = g_csr_src[ptr + i];
        acc += g_g2[s * 2 + c];
    }
#pragma unroll
    for (int off = 16; off >= 2; off >>= 1)
        acc += __shfl_down_sync(0xffffffffu, acc, off);     // parity preserved

    float dv = g_dinv[n];
    float z = fmaf(dv, acc, __ldg(&b2[c]));                 // valid on lanes 0,1
    float z0 = __shfl_sync(0xffffffffu, z, 0);
    float z1 = __shfl_sync(0xffffffffu, z, 1);
    if (lane == 0) {
        float m = fmaxf(z0, z1);
        float lse = m + logf(expf(z0 - m) + expf(z1 - m));
        *reinterpret_cast<float2*>(&out[n * 2]) = make_float2(z0 - lse, z1 - lse);
    }
}

extern "C" void kernel_launch(void* const* d_in, const int* in_sizes, int n_in,
                              void* d_out, int out_size) {
    const float* x      = (const float*)d_in[0];
    const int*   ei     = (const int*)d_in[1];      // int32 [2, E]
    const int*   ei_src = ei;
    const int*   ei_dst = ei + N_EDGES;
    const float* W1     = (const float*)d_in[2];
    const float* b1     = (const float*)d_in[3];
    const float* W2     = (const float*)d_in[4];
    const float* b2     = (const float*)d_in[5];
    float* out = (float*)d_out;

    const int TB = 256;
    k_zero   <<<NB_SCAN, TB>>>();
    k_cnt    <<<(N_EDGES + TB - 1) / TB, TB>>>(ei_dst);
    k_scan1  <<<NB_SCAN, TB>>>();
    k_scan2  <<<1, 512>>>();
    k_scan3  <<<NB_SCAN, TB>>>();
    k_fill   <<<(N_EDGES + TB - 1) / TB, TB>>>(ei_src, ei_dst);
    k_gemm1  <<<N_NODES / 16, 256>>>(x, W1);
    k_gather1<<<N_NODES / 8, 256>>>(b1, W2);      // 8 warps/block, warp per node
    k_gather2<<<N_NODES / 8, 256>>>(b2, out);
}